// round 13
// baseline (speedup 1.0000x reference)
#include <cuda_runtime.h>
#include <cuda_bf16.h>
#include <cuda_fp16.h>
#include <math.h>

#define IN_DIM 256
#define H_DIM 64
#define OUT_DIM 16
#define MAXN 50000
#define MAXE 800000
#define CSR_CAP 128
#define FAGCN_EPS 0.3f

// ---------------- scratch (no allocation allowed) ----------------
__device__ float  g_raw[MAXN * H_DIM];     // t1 output fp32 (plain)
__device__ __half g_raw16[MAXN * H_DIM];   // d[s] * relu  (y-table, layer 0)
__device__ __half g_x1h[MAXN * H_DIM];     // d[s] * x1    (y-table, layer 1)
__device__ int    g_cnt[MAXN];
__device__ int    g_csr[MAXN * CSR_CAP];
__device__ __half g_ecoef[MAXN * CSR_CAP];
__device__ float  g_d[MAXN];
__device__ float  g_a1[MAXN];
__device__ float  g_c1[MAXN];
__device__ float  g_a2[MAXN];
__device__ float  g_c2[MAXN];

// FMA-pipe tanh: Padé(13/6) on clamp(x, +-7.99), reciprocal via bit trick + 3 NR.
// Max error ~1e-6; no MUFU.
__device__ __forceinline__ float fast_tanh(float x) {
    float xc = fminf(fmaxf(x, -7.99f), 7.99f);
    float x2 = xc * xc;
    float p = -2.76076847742355e-16f;
    p = fmaf(p, x2, 2.00018790482477e-13f);
    p = fmaf(p, x2, -8.60467152213735e-11f);
    p = fmaf(p, x2, 5.12229709037114e-08f);
    p = fmaf(p, x2, 1.48572235717979e-05f);
    p = fmaf(p, x2, 6.37261928875436e-04f);
    p = fmaf(p, x2, 4.89352455891786e-03f);
    p = p * xc;
    float q = 1.19825839466702e-06f;
    q = fmaf(q, x2, 1.18534705686654e-04f);
    q = fmaf(q, x2, 2.26843463243900e-03f);
    q = fmaf(q, x2, 4.89352518554385e-03f);
    // reciprocal of q (q in [4.89e-3, ~1), positive)
    float r = __int_as_float(0x7EF127EAu - __float_as_uint(q));
    r = r * fmaf(-q, r, 2.0f);
    r = r * fmaf(-q, r, 2.0f);
    r = r * fmaf(-q, r, 2.0f);
    return p * r;
}

// ---------------- CSR build ----------------
__global__ void k_zero(int* __restrict__ p, int n) {
    int i = blockIdx.x * blockDim.x + threadIdx.x;
    if (i < n) p[i] = 0;
}

__global__ void k_fill(const int* __restrict__ src, const int* __restrict__ dst,
                       int* __restrict__ cnt, int* __restrict__ csr, int E) {
    int i = blockIdx.x * blockDim.x + threadIdx.x;
    if (i < E) {
        int t = dst[i];
        int pos = atomicAdd(&cnt[t], 1);
        if (pos < CSR_CAP) csr[t * CSR_CAP + pos] = src[i];
    }
}

// ---------------- t1: HMMA m16n8k16 + fused gate precompute + y-table ----------------
#define T1_BM 128
#define T1_WP 264
#define T1_HP 72
#define T1_SMEM ((64 * T1_WP + T1_BM * T1_HP) * 2)

__global__ void __launch_bounds__(256)
k_t1(const float* __restrict__ hin, const float* __restrict__ w,
     const float* __restrict__ b, float* __restrict__ out,
     __half* __restrict__ out16,
     const float* __restrict__ gw,
     const int* __restrict__ cnt,
     float* __restrict__ a1, float* __restrict__ c1,
     float* __restrict__ dvec, int N) {
    extern __shared__ __half smh[];
    __half* w16 = smh;
    __half* h16 = smh + 64 * T1_WP;
    int tx = threadIdx.x;
    int wp = tx >> 5;
    int lane = tx & 31;
    int g  = lane >> 2;
    int tq = lane & 3;

    const float4* w4 = (const float4*)w;
#pragma unroll
    for (int i = 0; i < 16; i++) {
        int idx = tx + i * 256;
        int j  = idx >> 6;
        int k4 = idx & 63;
        float4 v = w4[idx];
        __half2 p0 = __floats2half2_rn(v.x, v.y);
        __half2 p1 = __floats2half2_rn(v.z, v.w);
        uint2 u;
        u.x = *(unsigned*)&p0;
        u.y = *(unsigned*)&p1;
        *(uint2*)(w16 + j * T1_WP + k4 * 4) = u;
    }

    int n0 = blockIdx.x * T1_BM;
    float c[8][4];
#pragma unroll
    for (int nt = 0; nt < 8; nt++)
#pragma unroll
        for (int q = 0; q < 4; q++) c[nt][q] = 0.0f;

    for (int kt = 0; kt < 4; kt++) {
        __syncthreads();
#pragma unroll
        for (int i = 0; i < 8; i++) {
            int idx = tx + i * 256;
            int nl = idx >> 4;
            int k4 = idx & 15;
            int n  = n0 + nl;
            float4 v;
            if (n < N) v = *(const float4*)(hin + (size_t)n * IN_DIM + kt * 64 + k4 * 4);
            else       v = make_float4(0.f, 0.f, 0.f, 0.f);
            __half2 p0 = __floats2half2_rn(v.x, v.y);
            __half2 p1 = __floats2half2_rn(v.z, v.w);
            uint2 u;
            u.x = *(unsigned*)&p0;
            u.y = *(unsigned*)&p1;
            *(uint2*)(h16 + nl * T1_HP + k4 * 4) = u;
        }
        __syncthreads();

#pragma unroll
        for (int ks = 0; ks < 4; ks++) {
            int kl = ks * 16 + 2 * tq;
            const __half* arow = h16 + (wp * 16 + g) * T1_HP + kl;
            unsigned a0 = *(const unsigned*)(arow);
            unsigned a1f = *(const unsigned*)(arow + 8 * T1_HP);
            unsigned a2f = *(const unsigned*)(arow + 8);
            unsigned a3 = *(const unsigned*)(arow + 8 * T1_HP + 8);
            int kg = kt * 64 + ks * 16 + 2 * tq;
#pragma unroll
            for (int nt = 0; nt < 8; nt++) {
                const __half* brow = w16 + (nt * 8 + g) * T1_WP + kg;
                unsigned b0 = *(const unsigned*)(brow);
                unsigned b1 = *(const unsigned*)(brow + 8);
                asm volatile(
                    "mma.sync.aligned.m16n8k16.row.col.f32.f16.f16.f32 "
                    "{%0,%1,%2,%3}, {%4,%5,%6,%7}, {%8,%9}, {%0,%1,%2,%3};"
                    : "+f"(c[nt][0]), "+f"(c[nt][1]), "+f"(c[nt][2]), "+f"(c[nt][3])
                    : "r"(a0), "r"(a1f), "r"(a2f), "r"(a3), "r"(b0), "r"(b1));
            }
        }
    }

    int node0 = n0 + wp * 16 + g;
    int node1 = node0 + 8;
    float d0 = 0.f, d1 = 0.f;
    if (node0 < N) d0 = rsqrtf(fmaxf((float)cnt[node0], 1.0f));
    if (node1 < N) d1 = rsqrtf(fmaxf((float)cnt[node1], 1.0f));

    float pa0 = 0.f, pc0 = 0.f, pa1 = 0.f, pc1 = 0.f;
#pragma unroll
    for (int nt = 0; nt < 8; nt++) {
        int col = nt * 8 + 2 * tq;
        float2 bj = *(const float2*)(b + col);
        float2 r0, r1;
        r0.x = fmaxf(c[nt][0] + bj.x, 0.f);
        r0.y = fmaxf(c[nt][1] + bj.y, 0.f);
        r1.x = fmaxf(c[nt][2] + bj.x, 0.f);
        r1.y = fmaxf(c[nt][3] + bj.y, 0.f);
        if (node0 < N) {
            *(float2*)(out + (size_t)node0 * H_DIM + col) = r0;
            __half2 hh = __floats2half2_rn(d0 * r0.x, d0 * r0.y);
            *(unsigned*)(out16 + (size_t)node0 * H_DIM + col) = *(unsigned*)&hh;
        }
        if (node1 < N) {
            *(float2*)(out + (size_t)node1 * H_DIM + col) = r1;
            __half2 hh = __floats2half2_rn(d1 * r1.x, d1 * r1.y);
            *(unsigned*)(out16 + (size_t)node1 * H_DIM + col) = *(unsigned*)&hh;
        }
        float2 gwa = *(const float2*)(gw + col);
        float2 gwc = *(const float2*)(gw + 64 + col);
        pa0 += gwa.x * r0.x + gwa.y * r0.y;
        pc0 += gwc.x * r0.x + gwc.y * r0.y;
        pa1 += gwa.x * r1.x + gwa.y * r1.y;
        pc1 += gwc.x * r1.x + gwc.y * r1.y;
    }
#pragma unroll
    for (int o = 1; o <= 2; o <<= 1) {
        pa0 += __shfl_xor_sync(0xffffffffu, pa0, o);
        pc0 += __shfl_xor_sync(0xffffffffu, pc0, o);
        pa1 += __shfl_xor_sync(0xffffffffu, pa1, o);
        pc1 += __shfl_xor_sync(0xffffffffu, pc1, o);
    }
    if (tq == 0) {
        if (node0 < N) { a1[node0] = pa0; c1[node0] = pc0; dvec[node0] = d0; }
        if (node1 < N) { a1[node1] = pa1; c1[node1] = pc1; dvec[node1] = d1; }
    }
}

// ---------------- edge coefficient (warp per node, coalesced stores, FMA tanh) ----------------
__global__ void __launch_bounds__(256)
k_coef(const int* __restrict__ csr, const int* __restrict__ cnt,
       const float* __restrict__ a, const float* __restrict__ c,
       const float* __restrict__ gbp, int layer,
       __half* __restrict__ ecoef, int N) {
    int warp = (blockIdx.x * blockDim.x + threadIdx.x) >> 5;
    int lane = threadIdx.x & 31;
    if (warp >= N) return;
    int deg = min(cnt[warp], CSR_CAP);
    float base = a[warp] + gbp[layer];
    int st = warp * CSR_CAP;
    for (int ei = lane; ei < deg; ei += 32) {
        int s = csr[st + ei];
        float e = fast_tanh(base + c[s]);
        ecoef[st + ei] = __float2half(e);
    }
}

// ---------------- aggregation: 4 nodes/warp, y-table, d[t] applied once ----------------
__global__ void __launch_bounds__(256)
k_aggr(const __half* __restrict__ x, const float* __restrict__ raw,
       __half* __restrict__ xn_h,
       const int* __restrict__ csr, const int* __restrict__ cnt,
       const __half* __restrict__ ecoef, const float* __restrict__ dvec,
       const float* __restrict__ gw_next, float* __restrict__ a_next,
       float* __restrict__ c_next, int N) {
    int warp = (blockIdx.x * blockDim.x + threadIdx.x) >> 5;
    int lane = threadIdx.x & 31;
    int l = lane & 7;

    int t = warp * 4 + (lane >> 3);
    bool nvalid = (t < N);
    int tc = nvalid ? t : 0;

    int deg = nvalid ? min(cnt[tc], CSR_CAP) : 0;
    int start = tc * CSR_CAP;
    float dt = dvec[tc];

    int dm = deg;
    dm = max(dm, __shfl_xor_sync(0xffffffffu, dm, 8));
    dm = max(dm, __shfl_xor_sync(0xffffffffu, dm, 16));

    float sum[8];
#pragma unroll
    for (int q = 0; q < 8; q++) sum[q] = 0.0f;

    for (int b0 = 0; b0 < dm; b0 += 8) {
        int ei = b0 + l;
        int sb = 0;
        unsigned ep = 0;
        if (ei < deg) {
            sb = csr[start + ei];
            __half eh = ecoef[start + ei];
            __half2 e2 = __half2half2(eh);
            ep = *(unsigned*)&e2;
        }
        int mmax = min(8, dm - b0);
        __half2 h0 = __float2half2_rn(0.0f), h1 = h0, h2 = h0, h3 = h0;
        if (mmax == 8) {
#pragma unroll
            for (int bq = 0; bq < 8; bq++) {
                int srcl = (lane & 24) | bq;
                unsigned e = __shfl_sync(0xffffffffu, ep, srcl);
                int s  = __shfl_sync(0xffffffffu, sb, srcl);
                uint4 u = __ldg((const uint4*)(x + (size_t)s * 64 + l * 8));
                h0 = __hfma2(*(__half2*)&u.x, *(__half2*)&e, h0);
                h1 = __hfma2(*(__half2*)&u.y, *(__half2*)&e, h1);
                h2 = __hfma2(*(__half2*)&u.z, *(__half2*)&e, h2);
                h3 = __hfma2(*(__half2*)&u.w, *(__half2*)&e, h3);
            }
        } else {
            for (int bq = 0; bq < mmax; bq++) {
                int srcl = (lane & 24) | bq;
                unsigned e = __shfl_sync(0xffffffffu, ep, srcl);
                int s  = __shfl_sync(0xffffffffu, sb, srcl);
                uint4 u = __ldg((const uint4*)(x + (size_t)s * 64 + l * 8));
                h0 = __hfma2(*(__half2*)&u.x, *(__half2*)&e, h0);
                h1 = __hfma2(*(__half2*)&u.y, *(__half2*)&e, h1);
                h2 = __hfma2(*(__half2*)&u.z, *(__half2*)&e, h2);
                h3 = __hfma2(*(__half2*)&u.w, *(__half2*)&e, h3);
            }
        }
        float2 f0 = __half22float2(h0);
        float2 f1 = __half22float2(h1);
        float2 f2 = __half22float2(h2);
        float2 f3 = __half22float2(h3);
        sum[0] += f0.x; sum[1] += f0.y;
        sum[2] += f1.x; sum[3] += f1.y;
        sum[4] += f2.x; sum[5] += f2.y;
        sum[6] += f3.x; sum[7] += f3.y;
    }

    if (nvalid) {
        float4 r0 = *(const float4*)(raw + (size_t)t * 64 + l * 8);
        float4 r1 = *(const float4*)(raw + (size_t)t * 64 + l * 8 + 4);
        float acc[8];
        acc[0] = fmaf(dt, sum[0], FAGCN_EPS * r0.x);
        acc[1] = fmaf(dt, sum[1], FAGCN_EPS * r0.y);
        acc[2] = fmaf(dt, sum[2], FAGCN_EPS * r0.z);
        acc[3] = fmaf(dt, sum[3], FAGCN_EPS * r0.w);
        acc[4] = fmaf(dt, sum[4], FAGCN_EPS * r1.x);
        acc[5] = fmaf(dt, sum[5], FAGCN_EPS * r1.y);
        acc[6] = fmaf(dt, sum[6], FAGCN_EPS * r1.z);
        acc[7] = fmaf(dt, sum[7], FAGCN_EPS * r1.w);

        // y-table for next layer: d[t] * x1
        __half2 o0 = __floats2half2_rn(dt * acc[0], dt * acc[1]);
        __half2 o1 = __floats2half2_rn(dt * acc[2], dt * acc[3]);
        __half2 o2 = __floats2half2_rn(dt * acc[4], dt * acc[5]);
        __half2 o3 = __floats2half2_rn(dt * acc[6], dt * acc[7]);
        uint4 u;
        u.x = *(unsigned*)&o0; u.y = *(unsigned*)&o1;
        u.z = *(unsigned*)&o2; u.w = *(unsigned*)&o3;
        *(uint4*)(xn_h + (size_t)t * 64 + l * 8) = u;

        // fused next-layer gate precompute (plain x1)
        float4 wa0 = *(const float4*)(gw_next + l * 8);
        float4 wa1 = *(const float4*)(gw_next + l * 8 + 4);
        float4 wc0 = *(const float4*)(gw_next + 64 + l * 8);
        float4 wc1 = *(const float4*)(gw_next + 64 + l * 8 + 4);
        float pa = acc[0]*wa0.x + acc[1]*wa0.y + acc[2]*wa0.z + acc[3]*wa0.w
                 + acc[4]*wa1.x + acc[5]*wa1.y + acc[6]*wa1.z + acc[7]*wa1.w;
        float pc = acc[0]*wc0.x + acc[1]*wc0.y + acc[2]*wc0.z + acc[3]*wc0.w
                 + acc[4]*wc1.x + acc[5]*wc1.y + acc[6]*wc1.z + acc[7]*wc1.w;
#pragma unroll
        for (int o = 4; o; o >>= 1) {
            pa += __shfl_xor_sync(0xffffffffu, pa, o);
            pc += __shfl_xor_sync(0xffffffffu, pc, o);
        }
        if (l == 0) {
            a_next[t] = pa;
            c_next[t] = pc;
        }
    }
}

// ---------------- aggregation layer 1 + t2 + log_softmax ----------------
__global__ void __launch_bounds__(256)
k_aggr_out(const __half* __restrict__ x, const float* __restrict__ raw,
           const int* __restrict__ csr, const int* __restrict__ cnt,
           const __half* __restrict__ ecoef, const float* __restrict__ dvec,
           const float* __restrict__ w2, const float* __restrict__ b2,
           float* __restrict__ out, int N) {
    __shared__ float wS[16 * 64];
    __shared__ float xS[32][68];
    int tx = threadIdx.x;
#pragma unroll
    for (int i = 0; i < 4; i++) wS[tx + i * 256] = w2[tx + i * 256];

    int warp = (blockIdx.x * blockDim.x + tx) >> 5;
    int lane = tx & 31;
    int l = lane & 7;
    int nodeLocal = (tx >> 5) * 4 + (lane >> 3);

    int t = warp * 4 + (lane >> 3);
    bool nvalid = (t < N);
    int tc = nvalid ? t : 0;

    int deg = nvalid ? min(cnt[tc], CSR_CAP) : 0;
    int start = tc * CSR_CAP;
    float dt = dvec[tc];

    int dm = deg;
    dm = max(dm, __shfl_xor_sync(0xffffffffu, dm, 8));
    dm = max(dm, __shfl_xor_sync(0xffffffffu, dm, 16));

    float sum[8];
#pragma unroll
    for (int q = 0; q < 8; q++) sum[q] = 0.0f;

    for (int b0 = 0; b0 < dm; b0 += 8) {
        int ei = b0 + l;
        int sb = 0;
        unsigned ep = 0;
        if (ei < deg) {
            sb = csr[start + ei];
            __half eh = ecoef[start + ei];
            __half2 e2 = __half2half2(eh);
            ep = *(unsigned*)&e2;
        }
        int mmax = min(8, dm - b0);
        __half2 h0 = __float2half2_rn(0.0f), h1 = h0, h2 = h0, h3 = h0;
        if (mmax == 8) {
#pragma unroll
            for (int bq = 0; bq < 8; bq++) {
                int srcl = (lane & 24) | bq;
                unsigned e = __shfl_sync(0xffffffffu, ep, srcl);
                int s  = __shfl_sync(0xffffffffu, sb, srcl);
                uint4 u = __ldg((const uint4*)(x + (size_t)s * 64 + l * 8));
                h0 = __hfma2(*(__half2*)&u.x, *(__half2*)&e, h0);
                h1 = __hfma2(*(__half2*)&u.y, *(__half2*)&e, h1);
                h2 = __hfma2(*(__half2*)&u.z, *(__half2*)&e, h2);
                h3 = __hfma2(*(__half2*)&u.w, *(__half2*)&e, h3);
            }
        } else {
            for (int bq = 0; bq < mmax; bq++) {
                int srcl = (lane & 24) | bq;
                unsigned e = __shfl_sync(0xffffffffu, ep, srcl);
                int s  = __shfl_sync(0xffffffffu, sb, srcl);
                uint4 u = __ldg((const uint4*)(x + (size_t)s * 64 + l * 8));
                h0 = __hfma2(*(__half2*)&u.x, *(__half2*)&e, h0);
                h1 = __hfma2(*(__half2*)&u.y, *(__half2*)&e, h1);
                h2 = __hfma2(*(__half2*)&u.z, *(__half2*)&e, h2);
                h3 = __hfma2(*(__half2*)&u.w, *(__half2*)&e, h3);
            }
        }
        float2 f0 = __half22float2(h0);
        float2 f1 = __half22float2(h1);
        float2 f2 = __half22float2(h2);
        float2 f3 = __half22float2(h3);
        sum[0] += f0.x; sum[1] += f0.y;
        sum[2] += f1.x; sum[3] += f1.y;
        sum[4] += f2.x; sum[5] += f2.y;
        sum[6] += f3.x; sum[7] += f3.y;
    }

    {
        float4 r0 = nvalid ? *(const float4*)(raw + (size_t)t * 64 + l * 8)
                           : make_float4(0.f, 0.f, 0.f, 0.f);
        float4 r1 = nvalid ? *(const float4*)(raw + (size_t)t * 64 + l * 8 + 4)
                           : make_float4(0.f, 0.f, 0.f, 0.f);
        float4 o0, o1;
        o0.x = fmaf(dt, sum[0], FAGCN_EPS * r0.x);
        o0.y = fmaf(dt, sum[1], FAGCN_EPS * r0.y);
        o0.z = fmaf(dt, sum[2], FAGCN_EPS * r0.z);
        o0.w = fmaf(dt, sum[3], FAGCN_EPS * r0.w);
        o1.x = fmaf(dt, sum[4], FAGCN_EPS * r1.x);
        o1.y = fmaf(dt, sum[5], FAGCN_EPS * r1.y);
        o1.z = fmaf(dt, sum[6], FAGCN_EPS * r1.z);
        o1.w = fmaf(dt, sum[7], FAGCN_EPS * r1.w);
        *(float4*)(&xS[nodeLocal][l * 8])     = o0;
        *(float4*)(&xS[nodeLocal][l * 8 + 4]) = o1;
    }
    __syncthreads();

#pragma unroll
    for (int p = 0; p < 2; p++) {
        int idx = tx + p * 256;
        int nl2 = idx >> 4;
        int j = idx & 15;
        int node = blockIdx.x * 32 + nl2;
        const float4* xr = (const float4*)(&xS[nl2][0]);
        const float4* wr = (const float4*)(wS + j * 64);
        float logit = b2[j];
#pragma unroll
        for (int k = 0; k < 16; k++) {
            float4 av = xr[k];
            float4 wv = wr[k];
            logit += av.x * wv.x + av.y * wv.y + av.z * wv.z + av.w * wv.w;
        }
        float m = logit;
#pragma unroll
        for (int o = 8; o; o >>= 1) m = fmaxf(m, __shfl_xor_sync(0xffffffffu, m, o));
        float ex = expf(logit - m);
        float s = ex;
#pragma unroll
        for (int o = 8; o; o >>= 1) s += __shfl_xor_sync(0xffffffffu, s, o);
        if (node < N) out[(size_t)node * 16 + j] = logit - m - logf(s);
    }
}

// ---------------- launch ----------------
extern "C" void kernel_launch(void* const* d_in, const int* in_sizes, int n_in,
                              void* d_out, int out_size) {
    const float* h   = (const float*)d_in[0];
    const int*   src = (const int*)  d_in[1];
    const int*   dst = (const int*)  d_in[2];
    const float* t1w = (const float*)d_in[3];
    const float* t1b = (const float*)d_in[4];
    const float* gw  = (const float*)d_in[5];
    const float* gb  = (const float*)d_in[6];
    const float* t2w = (const float*)d_in[7];
    const float* t2b = (const float*)d_in[8];
    float* out = (float*)d_out;

    int N = in_sizes[0] / IN_DIM;
    int E = in_sizes[1];

    float *raw, *a1, *c1, *a2, *c2, *dv;
    __half *raw16, *x1h, *ecoef;
    int *cnt, *csr;
    cudaGetSymbolAddress((void**)&raw,   g_raw);
    cudaGetSymbolAddress((void**)&raw16, g_raw16);
    cudaGetSymbolAddress((void**)&x1h,   g_x1h);
    cudaGetSymbolAddress((void**)&cnt,   g_cnt);
    cudaGetSymbolAddress((void**)&csr,   g_csr);
    cudaGetSymbolAddress((void**)&ecoef, g_ecoef);
    cudaGetSymbolAddress((void**)&dv,    g_d);
    cudaGetSymbolAddress((void**)&a1,    g_a1);
    cudaGetSymbolAddress((void**)&c1,    g_c1);
    cudaGetSymbolAddress((void**)&a2,    g_a2);
    cudaGetSymbolAddress((void**)&c2,    g_c2);

    // order: zero(1), fill(2), t1(3), coef0(4 <- ncu slot), aggr0(5), coef1(6), aggr_out(7)
    k_zero<<<(N + 255) / 256, 256>>>(cnt, N);
    k_fill<<<(E + 255) / 256, 256>>>(src, dst, cnt, csr, E);

    cudaFuncSetAttribute(k_t1, cudaFuncAttributeMaxDynamicSharedMemorySize, T1_SMEM);
    k_t1<<<(N + T1_BM - 1) / T1_BM, 256, T1_SMEM>>>(h, t1w, t1b, raw, raw16,
                                                    gw, cnt, a1, c1, dv, N);

    int cblk = (N * 32 + 255) / 256;
    int ablk = (N + 31) / 32;

    k_coef<<<cblk, 256>>>(csr, cnt, a1, c1, gb, 0, ecoef, N);
    k_aggr<<<ablk, 256>>>(raw16, raw, x1h, csr, cnt, ecoef, dv,
                          gw + 128, a2, c2, N);
    k_coef<<<cblk, 256>>>(csr, cnt, a2, c2, gb, 1, ecoef, N);
    k_aggr_out<<<ablk, 256>>>(x1h, raw, csr, cnt, ecoef, dv, t2w, t2b, out, N);
}

// round 14
// speedup vs baseline: 1.1509x; 1.1509x over previous
#include <cuda_runtime.h>
#include <cuda_bf16.h>
#include <cuda_fp16.h>
#include <math.h>

#define IN_DIM 256
#define H_DIM 64
#define OUT_DIM 16
#define MAXN 50000
#define MAXE 800000
#define CSR_CAP 128
#define FAGCN_EPS 0.3f

// ---------------- scratch (no allocation allowed) ----------------
__device__ float  g_raw[MAXN * H_DIM];
__device__ __half g_raw16[MAXN * H_DIM];
__device__ __half g_x1h[MAXN * H_DIM];
__device__ int    g_cnt[MAXN];
__device__ int    g_csr[MAXN * CSR_CAP];
__device__ __half g_ecoef[MAXN * CSR_CAP];
__device__ float  g_a1[MAXN];
__device__ float2 g_cd1[MAXN];
__device__ float  g_a2[MAXN];
__device__ float2 g_cd2[MAXN];

__device__ __forceinline__ float tanh_approx(float x) {
    float r;
    asm("tanh.approx.f32 %0, %1;" : "=f"(r) : "f"(x));
    return r;
}

// ---------------- CSR build ----------------
__global__ void k_zero(int* __restrict__ p, int n) {
    int i = blockIdx.x * blockDim.x + threadIdx.x;
    if (i < n) p[i] = 0;
}

__global__ void k_fill(const int* __restrict__ src, const int* __restrict__ dst,
                       int* __restrict__ cnt, int* __restrict__ csr, int E) {
    int i = blockIdx.x * blockDim.x + threadIdx.x;
    if (i < E) {
        int t = dst[i];
        int pos = atomicAdd(&cnt[t], 1);
        if (pos < CSR_CAP) csr[t * CSR_CAP + pos] = src[i];
    }
}

// ---------------- t1: HMMA m16n8k16 + fused gate precompute ----------------
#define T1_BM 128
#define T1_WP 264
#define T1_HP 72
#define T1_SMEM ((64 * T1_WP + T1_BM * T1_HP) * 2)

__global__ void __launch_bounds__(256)
k_t1(const float* __restrict__ hin, const float* __restrict__ w,
     const float* __restrict__ b, float* __restrict__ out,
     __half* __restrict__ out16,
     const float* __restrict__ gw,
     const int* __restrict__ cnt,
     float* __restrict__ a1, float2* __restrict__ cd1, int N) {
    extern __shared__ __half smh[];
    __half* w16 = smh;
    __half* h16 = smh + 64 * T1_WP;
    int tx = threadIdx.x;
    int wp = tx >> 5;
    int lane = tx & 31;
    int g  = lane >> 2;
    int tq = lane & 3;

    const float4* w4 = (const float4*)w;
#pragma unroll
    for (int i = 0; i < 16; i++) {
        int idx = tx + i * 256;
        int j  = idx >> 6;
        int k4 = idx & 63;
        float4 v = w4[idx];
        __half2 p0 = __floats2half2_rn(v.x, v.y);
        __half2 p1 = __floats2half2_rn(v.z, v.w);
        uint2 u;
        u.x = *(unsigned*)&p0;
        u.y = *(unsigned*)&p1;
        *(uint2*)(w16 + j * T1_WP + k4 * 4) = u;
    }

    int n0 = blockIdx.x * T1_BM;
    float c[8][4];
#pragma unroll
    for (int nt = 0; nt < 8; nt++)
#pragma unroll
        for (int q = 0; q < 4; q++) c[nt][q] = 0.0f;

    for (int kt = 0; kt < 4; kt++) {
        __syncthreads();
#pragma unroll
        for (int i = 0; i < 8; i++) {
            int idx = tx + i * 256;
            int nl = idx >> 4;
            int k4 = idx & 15;
            int n  = n0 + nl;
            float4 v;
            if (n < N) v = *(const float4*)(hin + (size_t)n * IN_DIM + kt * 64 + k4 * 4);
            else       v = make_float4(0.f, 0.f, 0.f, 0.f);
            __half2 p0 = __floats2half2_rn(v.x, v.y);
            __half2 p1 = __floats2half2_rn(v.z, v.w);
            uint2 u;
            u.x = *(unsigned*)&p0;
            u.y = *(unsigned*)&p1;
            *(uint2*)(h16 + nl * T1_HP + k4 * 4) = u;
        }
        __syncthreads();

#pragma unroll
        for (int ks = 0; ks < 4; ks++) {
            int kl = ks * 16 + 2 * tq;
            const __half* arow = h16 + (wp * 16 + g) * T1_HP + kl;
            unsigned a0 = *(const unsigned*)(arow);
            unsigned a1f = *(const unsigned*)(arow + 8 * T1_HP);
            unsigned a2f = *(const unsigned*)(arow + 8);
            unsigned a3 = *(const unsigned*)(arow + 8 * T1_HP + 8);
            int kg = kt * 64 + ks * 16 + 2 * tq;
#pragma unroll
            for (int nt = 0; nt < 8; nt++) {
                const __half* brow = w16 + (nt * 8 + g) * T1_WP + kg;
                unsigned b0 = *(const unsigned*)(brow);
                unsigned b1 = *(const unsigned*)(brow + 8);
                asm volatile(
                    "mma.sync.aligned.m16n8k16.row.col.f32.f16.f16.f32 "
                    "{%0,%1,%2,%3}, {%4,%5,%6,%7}, {%8,%9}, {%0,%1,%2,%3};"
                    : "+f"(c[nt][0]), "+f"(c[nt][1]), "+f"(c[nt][2]), "+f"(c[nt][3])
                    : "r"(a0), "r"(a1f), "r"(a2f), "r"(a3), "r"(b0), "r"(b1));
            }
        }
    }

    int node0 = n0 + wp * 16 + g;
    int node1 = node0 + 8;
    float pa0 = 0.f, pc0 = 0.f, pa1 = 0.f, pc1 = 0.f;
#pragma unroll
    for (int nt = 0; nt < 8; nt++) {
        int col = nt * 8 + 2 * tq;
        float2 bj = *(const float2*)(b + col);
        float2 r0, r1;
        r0.x = fmaxf(c[nt][0] + bj.x, 0.f);
        r0.y = fmaxf(c[nt][1] + bj.y, 0.f);
        r1.x = fmaxf(c[nt][2] + bj.x, 0.f);
        r1.y = fmaxf(c[nt][3] + bj.y, 0.f);
        if (node0 < N) {
            *(float2*)(out + (size_t)node0 * H_DIM + col) = r0;
            __half2 hh = __floats2half2_rn(r0.x, r0.y);
            *(unsigned*)(out16 + (size_t)node0 * H_DIM + col) = *(unsigned*)&hh;
        }
        if (node1 < N) {
            *(float2*)(out + (size_t)node1 * H_DIM + col) = r1;
            __half2 hh = __floats2half2_rn(r1.x, r1.y);
            *(unsigned*)(out16 + (size_t)node1 * H_DIM + col) = *(unsigned*)&hh;
        }
        float2 gwa = *(const float2*)(gw + col);
        float2 gwc = *(const float2*)(gw + 64 + col);
        pa0 += gwa.x * r0.x + gwa.y * r0.y;
        pc0 += gwc.x * r0.x + gwc.y * r0.y;
        pa1 += gwa.x * r1.x + gwa.y * r1.y;
        pc1 += gwc.x * r1.x + gwc.y * r1.y;
    }
#pragma unroll
    for (int o = 1; o <= 2; o <<= 1) {
        pa0 += __shfl_xor_sync(0xffffffffu, pa0, o);
        pc0 += __shfl_xor_sync(0xffffffffu, pc0, o);
        pa1 += __shfl_xor_sync(0xffffffffu, pa1, o);
        pc1 += __shfl_xor_sync(0xffffffffu, pc1, o);
    }
    if (tq == 0) {
        if (node0 < N) {
            a1[node0] = pa0;
            float d = rsqrtf(fmaxf((float)cnt[node0], 1.0f));
            cd1[node0] = make_float2(pc0, d);
        }
        if (node1 < N) {
            a1[node1] = pa1;
            float d = rsqrtf(fmaxf((float)cnt[node1], 1.0f));
            cd1[node1] = make_float2(pc1, d);
        }
    }
}

// ---------------- edge coefficient precompute (4 nodes per warp) ----------------
// 8-lane quarter owns one node; deg~16 -> 2 edges/lane. Warp count N/4 ->
// ~3.3 latency waves instead of 13.
__global__ void __launch_bounds__(256)
k_coef(const int* __restrict__ csr, const int* __restrict__ cnt,
       const float* __restrict__ a, const float2* __restrict__ cd,
       const float* __restrict__ gbp, int layer,
       __half* __restrict__ ecoef, int N) {
    int warp = (blockIdx.x * blockDim.x + threadIdx.x) >> 5;
    int lane = threadIdx.x & 31;
    int l = lane & 7;
    int t = warp * 4 + (lane >> 3);
    if (t >= N) return;
    int deg = min(cnt[t], CSR_CAP);
    float2 cdt = cd[t];
    float base = a[t] + gbp[layer];
    float dt = cdt.y;
    int st = t * CSR_CAP;
    for (int ei = l; ei < deg; ei += 8) {
        int s = csr[st + ei];
        float2 cs = cd[s];
        float e = tanh_approx(base + cs.x) * dt * cs.y;
        ecoef[st + ei] = __float2half(e);
    }
}

// ---------------- aggregation: 4 nodes/warp, precomputed coefs ----------------
__global__ void __launch_bounds__(256)
k_aggr(const __half* __restrict__ x, const float* __restrict__ raw,
       __half* __restrict__ xn_h,
       const int* __restrict__ csr, const int* __restrict__ cnt,
       const __half* __restrict__ ecoef, const float2* __restrict__ cd,
       const float* __restrict__ gw_next, float* __restrict__ a_next,
       float2* __restrict__ cd_next, int N) {
    int warp = (blockIdx.x * blockDim.x + threadIdx.x) >> 5;
    int lane = threadIdx.x & 31;
    int l = lane & 7;

    int t = warp * 4 + (lane >> 3);
    bool nvalid = (t < N);
    int tc = nvalid ? t : 0;

    int deg = nvalid ? min(cnt[tc], CSR_CAP) : 0;
    int start = tc * CSR_CAP;

    int dm = deg;
    dm = max(dm, __shfl_xor_sync(0xffffffffu, dm, 8));
    dm = max(dm, __shfl_xor_sync(0xffffffffu, dm, 16));

    float acc[8];
    {
        float4 r0 = nvalid ? *(const float4*)(raw + (size_t)t * 64 + l * 8)
                           : make_float4(0.f, 0.f, 0.f, 0.f);
        float4 r1 = nvalid ? *(const float4*)(raw + (size_t)t * 64 + l * 8 + 4)
                           : make_float4(0.f, 0.f, 0.f, 0.f);
        acc[0] = FAGCN_EPS * r0.x; acc[1] = FAGCN_EPS * r0.y;
        acc[2] = FAGCN_EPS * r0.z; acc[3] = FAGCN_EPS * r0.w;
        acc[4] = FAGCN_EPS * r1.x; acc[5] = FAGCN_EPS * r1.y;
        acc[6] = FAGCN_EPS * r1.z; acc[7] = FAGCN_EPS * r1.w;
    }

    for (int b0 = 0; b0 < dm; b0 += 8) {
        int ei = b0 + l;
        int sb = 0;
        unsigned ep = 0;
        if (ei < deg) {
            sb = csr[start + ei];
            __half eh = ecoef[start + ei];
            __half2 e2 = __half2half2(eh);
            ep = *(unsigned*)&e2;
        }
        int mmax = min(8, dm - b0);
        __half2 h0 = __float2half2_rn(0.0f), h1 = h0, h2 = h0, h3 = h0;
        if (mmax == 8) {
#pragma unroll
            for (int bq = 0; bq < 8; bq++) {
                int srcl = (lane & 24) | bq;
                unsigned e = __shfl_sync(0xffffffffu, ep, srcl);
                int s  = __shfl_sync(0xffffffffu, sb, srcl);
                uint4 u = __ldg((const uint4*)(x + (size_t)s * 64 + l * 8));
                h0 = __hfma2(*(__half2*)&u.x, *(__half2*)&e, h0);
                h1 = __hfma2(*(__half2*)&u.y, *(__half2*)&e, h1);
                h2 = __hfma2(*(__half2*)&u.z, *(__half2*)&e, h2);
                h3 = __hfma2(*(__half2*)&u.w, *(__half2*)&e, h3);
            }
        } else {
            for (int bq = 0; bq < mmax; bq++) {
                int srcl = (lane & 24) | bq;
                unsigned e = __shfl_sync(0xffffffffu, ep, srcl);
                int s  = __shfl_sync(0xffffffffu, sb, srcl);
                uint4 u = __ldg((const uint4*)(x + (size_t)s * 64 + l * 8));
                h0 = __hfma2(*(__half2*)&u.x, *(__half2*)&e, h0);
                h1 = __hfma2(*(__half2*)&u.y, *(__half2*)&e, h1);
                h2 = __hfma2(*(__half2*)&u.z, *(__half2*)&e, h2);
                h3 = __hfma2(*(__half2*)&u.w, *(__half2*)&e, h3);
            }
        }
        float2 f0 = __half22float2(h0);
        float2 f1 = __half22float2(h1);
        float2 f2 = __half22float2(h2);
        float2 f3 = __half22float2(h3);
        acc[0] += f0.x; acc[1] += f0.y;
        acc[2] += f1.x; acc[3] += f1.y;
        acc[4] += f2.x; acc[5] += f2.y;
        acc[6] += f3.x; acc[7] += f3.y;
    }

    if (nvalid) {
        __half2 o0 = __floats2half2_rn(acc[0], acc[1]);
        __half2 o1 = __floats2half2_rn(acc[2], acc[3]);
        __half2 o2 = __floats2half2_rn(acc[4], acc[5]);
        __half2 o3 = __floats2half2_rn(acc[6], acc[7]);
        uint4 u;
        u.x = *(unsigned*)&o0; u.y = *(unsigned*)&o1;
        u.z = *(unsigned*)&o2; u.w = *(unsigned*)&o3;
        *(uint4*)(xn_h + (size_t)t * 64 + l * 8) = u;

        float4 wa0 = *(const float4*)(gw_next + l * 8);
        float4 wa1 = *(const float4*)(gw_next + l * 8 + 4);
        float4 wc0 = *(const float4*)(gw_next + 64 + l * 8);
        float4 wc1 = *(const float4*)(gw_next + 64 + l * 8 + 4);
        float pa = acc[0]*wa0.x + acc[1]*wa0.y + acc[2]*wa0.z + acc[3]*wa0.w
                 + acc[4]*wa1.x + acc[5]*wa1.y + acc[6]*wa1.z + acc[7]*wa1.w;
        float pc = acc[0]*wc0.x + acc[1]*wc0.y + acc[2]*wc0.z + acc[3]*wc0.w
                 + acc[4]*wc1.x + acc[5]*wc1.y + acc[6]*wc1.z + acc[7]*wc1.w;
#pragma unroll
        for (int o = 4; o; o >>= 1) {
            pa += __shfl_xor_sync(0xffffffffu, pa, o);
            pc += __shfl_xor_sync(0xffffffffu, pc, o);
        }
        if (l == 0) {
            a_next[t] = pa;
            cd_next[t] = make_float2(pc, cd[t].y);
        }
    }
}

// ---------------- aggregation layer 1 + t2 + log_softmax ----------------
__global__ void __launch_bounds__(256)
k_aggr_out(const __half* __restrict__ x, const float* __restrict__ raw,
           const int* __restrict__ csr, const int* __restrict__ cnt,
           const __half* __restrict__ ecoef,
           const float* __restrict__ w2, const float* __restrict__ b2,
           float* __restrict__ out, int N) {
    __shared__ float wS[16 * 64];
    __shared__ float xS[32][68];
    int tx = threadIdx.x;
#pragma unroll
    for (int i = 0; i < 4; i++) wS[tx + i * 256] = w2[tx + i * 256];

    int warp = (blockIdx.x * blockDim.x + tx) >> 5;
    int lane = tx & 31;
    int l = lane & 7;
    int nodeLocal = (tx >> 5) * 4 + (lane >> 3);

    int t = warp * 4 + (lane >> 3);
    bool nvalid = (t < N);
    int tc = nvalid ? t : 0;

    int deg = nvalid ? min(cnt[tc], CSR_CAP) : 0;
    int start = tc * CSR_CAP;

    int dm = deg;
    dm = max(dm, __shfl_xor_sync(0xffffffffu, dm, 8));
    dm = max(dm, __shfl_xor_sync(0xffffffffu, dm, 16));

    float acc[8];
    {
        float4 r0 = nvalid ? *(const float4*)(raw + (size_t)t * 64 + l * 8)
                           : make_float4(0.f, 0.f, 0.f, 0.f);
        float4 r1 = nvalid ? *(const float4*)(raw + (size_t)t * 64 + l * 8 + 4)
                           : make_float4(0.f, 0.f, 0.f, 0.f);
        acc[0] = FAGCN_EPS * r0.x; acc[1] = FAGCN_EPS * r0.y;
        acc[2] = FAGCN_EPS * r0.z; acc[3] = FAGCN_EPS * r0.w;
        acc[4] = FAGCN_EPS * r1.x; acc[5] = FAGCN_EPS * r1.y;
        acc[6] = FAGCN_EPS * r1.z; acc[7] = FAGCN_EPS * r1.w;
    }

    for (int b0 = 0; b0 < dm; b0 += 8) {
        int ei = b0 + l;
        int sb = 0;
        unsigned ep = 0;
        if (ei < deg) {
            sb = csr[start + ei];
            __half eh = ecoef[start + ei];
            __half2 e2 = __half2half2(eh);
            ep = *(unsigned*)&e2;
        }
        int mmax = min(8, dm - b0);
        __half2 h0 = __float2half2_rn(0.0f), h1 = h0, h2 = h0, h3 = h0;
        if (mmax == 8) {
#pragma unroll
            for (int bq = 0; bq < 8; bq++) {
                int srcl = (lane & 24) | bq;
                unsigned e = __shfl_sync(0xffffffffu, ep, srcl);
                int s  = __shfl_sync(0xffffffffu, sb, srcl);
                uint4 u = __ldg((const uint4*)(x + (size_t)s * 64 + l * 8));
                h0 = __hfma2(*(__half2*)&u.x, *(__half2*)&e, h0);
                h1 = __hfma2(*(__half2*)&u.y, *(__half2*)&e, h1);
                h2 = __hfma2(*(__half2*)&u.z, *(__half2*)&e, h2);
                h3 = __hfma2(*(__half2*)&u.w, *(__half2*)&e, h3);
            }
        } else {
            for (int bq = 0; bq < mmax; bq++) {
                int srcl = (lane & 24) | bq;
                unsigned e = __shfl_sync(0xffffffffu, ep, srcl);
                int s  = __shfl_sync(0xffffffffu, sb, srcl);
                uint4 u = __ldg((const uint4*)(x + (size_t)s * 64 + l * 8));
                h0 = __hfma2(*(__half2*)&u.x, *(__half2*)&e, h0);
                h1 = __hfma2(*(__half2*)&u.y, *(__half2*)&e, h1);
                h2 = __hfma2(*(__half2*)&u.z, *(__half2*)&e, h2);
                h3 = __hfma2(*(__half2*)&u.w, *(__half2*)&e, h3);
            }
        }
        float2 f0 = __half22float2(h0);
        float2 f1 = __half22float2(h1);
        float2 f2 = __half22float2(h2);
        float2 f3 = __half22float2(h3);
        acc[0] += f0.x; acc[1] += f0.y;
        acc[2] += f1.x; acc[3] += f1.y;
        acc[4] += f2.x; acc[5] += f2.y;
        acc[6] += f3.x; acc[7] += f3.y;
    }

    *(float4*)(&xS[nodeLocal][l * 8])     = make_float4(acc[0], acc[1], acc[2], acc[3]);
    *(float4*)(&xS[nodeLocal][l * 8 + 4]) = make_float4(acc[4], acc[5], acc[6], acc[7]);
    __syncthreads();

#pragma unroll
    for (int p = 0; p < 2; p++) {
        int idx = tx + p * 256;
        int nl2 = idx >> 4;
        int j = idx & 15;
        int node = blockIdx.x * 32 + nl2;
        const float4* xr = (const float4*)(&xS[nl2][0]);
        const float4* wr = (const float4*)(wS + j * 64);
        float logit = b2[j];
#pragma unroll
        for (int k = 0; k < 16; k++) {
            float4 av = xr[k];
            float4 wv = wr[k];
            logit += av.x * wv.x + av.y * wv.y + av.z * wv.z + av.w * wv.w;
        }
        float m = logit;
#pragma unroll
        for (int o = 8; o; o >>= 1) m = fmaxf(m, __shfl_xor_sync(0xffffffffu, m, o));
        float ex = expf(logit - m);
        float s = ex;
#pragma unroll
        for (int o = 8; o; o >>= 1) s += __shfl_xor_sync(0xffffffffu, s, o);
        if (node < N) out[(size_t)node * 16 + j] = logit - m - logf(s);
    }
}

// ---------------- launch ----------------
extern "C" void kernel_launch(void* const* d_in, const int* in_sizes, int n_in,
                              void* d_out, int out_size) {
    const float* h   = (const float*)d_in[0];
    const int*   src = (const int*)  d_in[1];
    const int*   dst = (const int*)  d_in[2];
    const float* t1w = (const float*)d_in[3];
    const float* t1b = (const float*)d_in[4];
    const float* gw  = (const float*)d_in[5];
    const float* gb  = (const float*)d_in[6];
    const float* t2w = (const float*)d_in[7];
    const float* t2b = (const float*)d_in[8];
    float* out = (float*)d_out;

    int N = in_sizes[0] / IN_DIM;
    int E = in_sizes[1];

    float *raw, *a1, *a2;
    __half *raw16, *x1h, *ecoef;
    float2 *cd1, *cd2;
    int *cnt, *csr;
    cudaGetSymbolAddress((void**)&raw,   g_raw);
    cudaGetSymbolAddress((void**)&raw16, g_raw16);
    cudaGetSymbolAddress((void**)&x1h,   g_x1h);
    cudaGetSymbolAddress((void**)&cnt,   g_cnt);
    cudaGetSymbolAddress((void**)&csr,   g_csr);
    cudaGetSymbolAddress((void**)&ecoef, g_ecoef);
    cudaGetSymbolAddress((void**)&a1,    g_a1);
    cudaGetSymbolAddress((void**)&a2,    g_a2);
    cudaGetSymbolAddress((void**)&cd1,   g_cd1);
    cudaGetSymbolAddress((void**)&cd2,   g_cd2);

    // order: zero(1), fill(2), t1(3), coef0(4 <- ncu slot), aggr0(5), coef1(6), aggr_out(7)
    k_zero<<<(N + 255) / 256, 256>>>(cnt, N);
    k_fill<<<(E + 255) / 256, 256>>>(src, dst, cnt, csr, E);

    cudaFuncSetAttribute(k_t1, cudaFuncAttributeMaxDynamicSharedMemorySize, T1_SMEM);
    k_t1<<<(N + T1_BM - 1) / T1_BM, 256, T1_SMEM>>>(h, t1w, t1b, raw, raw16,
                                                    gw, cnt, a1, cd1, N);

    int cblk = (N + 31) / 32;   // 8 warps x 4 nodes
    int ablk = (N + 31) / 32;

    k_coef<<<cblk, 256>>>(csr, cnt, a1, cd1, gb, 0, ecoef, N);
    k_aggr<<<ablk, 256>>>(raw16, raw, x1h, csr, cnt, ecoef, cd1,
                          gw + 128, a2, cd2, N);
    k_coef<<<cblk, 256>>>(csr, cnt, a2, cd2, gb, 1, ecoef, N);
    k_aggr_out<<<ablk, 256>>>(x1h, raw, csr, cnt, ecoef, t2w, t2b, out, N);
}